// round 14
// baseline (speedup 1.0000x reference)
#include <cuda_runtime.h>
#include <cuda_fp16.h>

#define BQ 4
#define LQ 2048
#define DM 64
#define ED 128
#define NQ 32
#define DCV 16
#define DTR 4
#define RQ 68            // DTR + 2*N
#define EPSQ 1e-5f
#define LOG2EF 1.4426950408889634f

#define CH 256           // steps per chunk (k3)
#define NCH 8            // chunks
#define EG 16            // e-channels per scan block

// ---------------- scratch (device globals; no allocation allowed) ----------------
__device__ float  g_h[BQ * LQ * DM];               // residual stream
__device__ float  g_xz[BQ * LQ * 2 * ED];          // in_proj output (b,l,2e)
__device__ float2 g_dx2[BQ * ED * LQ];             // {delta, delta*xc}  (b,e,l)
__device__ float2 g_gate2[BQ * ED * LQ];           // {silu(z), Dp*xc*silu(z)} (b,e,l)
__device__ unsigned g_bcTp[BQ * NCH * CH * NQ];    // {B lo, C hi} fp16x2, (b,chunk,t,n)
__device__ float  g_yout[BQ * ED * LQ];            // RAW scan output (b,e,l)
__device__ float2 g_carry[BQ * ED * NCH * NQ];     // {h_final, P}

__device__ __forceinline__ float ex2(float x) {
    float r; asm("ex2.approx.ftz.f32 %0, %1;" : "=f"(r) : "f"(x)); return r;
}

// ================= K1: rmsnorm + in_proj (layer 0 only) =================
#define K1_SMEM_FLOATS (64 * 257 + 32 * 68)
#define K1_SMEM_BYTES  (K1_SMEM_FLOATS * 4)

__global__ void __launch_bounds__(256, 2) k1_rms_inproj(
    const float* __restrict__ hin,
    const float* __restrict__ inw,   // (256, 64)
    const float* __restrict__ inb,
    const float* __restrict__ nw)
{
    extern __shared__ float sm1[];
    float* s_w    = sm1;              // [k=64][c=256] pad 257
    float* s_nrow = sm1 + 64 * 257;   // [l=32][k=64] pad 68

    int b  = blockIdx.x >> 6;
    int l0 = (blockIdx.x & 63) << 5;
    int tid = threadIdx.x;
    int lane = tid & 31, wid = tid >> 5;

    for (int i = tid; i < 256 * 64; i += 256)
        s_w[(i & 63) * 257 + (i >> 6)] = inw[i];

    #pragma unroll
    for (int il = 0; il < 4; ++il) {
        int l = wid * 4 + il;
        const float* hr = hin + ((size_t)(b * LQ + l0 + l)) * DM;
        float v0 = hr[lane], v1 = hr[lane + 32];
        float ss = v0 * v0 + v1 * v1;
        #pragma unroll
        for (int s = 16; s; s >>= 1) ss += __shfl_xor_sync(~0u, ss, s);
        float r = rsqrtf(ss * (1.0f / DM) + EPSQ);
        s_nrow[l * 68 + lane]      = v0 * r * nw[lane];
        s_nrow[l * 68 + lane + 32] = v1 * r * nw[lane + 32];
    }
    __syncthreads();

    int c = tid;
    float acc[32];
    #pragma unroll
    for (int l = 0; l < 32; ++l) acc[l] = 0.f;

    #pragma unroll 2
    for (int k4 = 0; k4 < 16; ++k4) {
        float w0 = s_w[(k4 * 4 + 0) * 257 + c];
        float w1 = s_w[(k4 * 4 + 1) * 257 + c];
        float w2 = s_w[(k4 * 4 + 2) * 257 + c];
        float w3 = s_w[(k4 * 4 + 3) * 257 + c];
        #pragma unroll
        for (int l = 0; l < 32; ++l) {
            float4 x = *(const float4*)&s_nrow[l * 68 + k4 * 4];
            acc[l] += w0 * x.x + w1 * x.y + w2 * x.z + w3 * x.w;
        }
    }
    float bb = inb[c];
    float* xzp = g_xz + ((size_t)(b * LQ + l0)) * 256 + c;
    #pragma unroll
    for (int l = 0; l < 32; ++l) xzp[(size_t)l * 256] = acc[l] + bb;
}

// ================= K41: gate + out_proj + residual + rmsnorm + in_proj =================
// grid: B * (L/16) = 512 blocks (3.46/SM, single wave at 4/SM), 256 threads.
// smem (floats): phase A: s_wT[128*65]@0, s_yT[128*20]@8320 (ends 10880)
//                phase B: s_w2[32*257]@0 (2 k-tiles, aliases), s_nrow[16*68]@10880 (ends 11968)
#define K41_SMEM_FLOATS 11968
#define K41_SMEM_BYTES  (K41_SMEM_FLOATS * 4)

__global__ void __launch_bounds__(256, 4) k41_out_rms_in(
    const float* __restrict__ ow,    // (64, 128)  layer i-1
    const float* __restrict__ ob,
    const float* __restrict__ hin,
    float* __restrict__ hout,        // g_h
    const float* __restrict__ inw,   // (256, 64)  layer i
    const float* __restrict__ inb,
    const float* __restrict__ nw)
{
    extern __shared__ float smf[];
    float* s_wT   = smf;              // [k=128][d=64] pad 65
    float* s_yT   = smf + 128 * 65;   // [e=128][l=16] pad 20
    float* s_w2   = smf;              // phase B: [k=32][c=256] pad 257 (k-tile)
    float* s_nrow = smf + 10880;      // [l=16][k=64] pad 68

    int b  = blockIdx.x >> 7;
    int l0 = (blockIdx.x & 127) << 4;
    int tid = threadIdx.x;
    int lane = tid & 31, wid = tid >> 5;

    // ---- phase A: stage out_proj weights (transposed) + gated y ----
    for (int i = tid; i < 64 * 128; i += 256)
        s_wT[(i & 127) * 65 + (i >> 7)] = ow[i];
    for (int i = tid; i < 128 * 16; i += 256) {
        int e = i >> 4, l = i & 15;
        size_t idx = ((size_t)(b * ED + e)) * LQ + l0 + l;
        float yr = g_yout[idx];
        float2 g = __ldg(&g_gate2[idx]);
        s_yT[e * 20 + l] = fmaf(yr, g.x, g.y);
    }
    __syncthreads();

    // out_proj GEMM: thread = (d, l-group of 4)
    int d = tid & 63, lg = tid >> 6;
    float acc0 = 0.f, acc1 = 0.f, acc2 = 0.f, acc3 = 0.f;

    #pragma unroll 4
    for (int k = 0; k < 128; ++k) {
        float w = s_wT[k * 65 + d];
        float4 x = *(const float4*)&s_yT[k * 20 + lg * 4];
        acc0 += w * x.x; acc1 += w * x.y; acc2 += w * x.z; acc3 += w * x.w;
    }

    float bias = ob[d];
    {
        float a[4] = {acc0, acc1, acc2, acc3};
        #pragma unroll
        for (int j = 0; j < 4; ++j) {
            int l = lg * 4 + j;
            size_t idx = ((size_t)(b * LQ + l0 + l)) * DM + d;
            float hv = hin[idx] + bias + a[j];
            hout[idx] = hv;
            s_nrow[l * 68 + d] = hv;      // disjoint region
        }
    }
    __syncthreads();

    // ---- rmsnorm rows in place: 8 warps x 2 rows ----
    #pragma unroll
    for (int il = 0; il < 2; ++il) {
        int l = wid * 2 + il;
        float v0 = s_nrow[l * 68 + lane], v1 = s_nrow[l * 68 + lane + 32];
        float ss = v0 * v0 + v1 * v1;
        #pragma unroll
        for (int s = 16; s; s >>= 1) ss += __shfl_xor_sync(~0u, ss, s);
        float r = rsqrtf(ss * (1.0f / DM) + EPSQ);
        s_nrow[l * 68 + lane]      = v0 * r * nw[lane];
        s_nrow[l * 68 + lane + 32] = v1 * r * nw[lane + 32];
    }
    __syncthreads();

    // ---- phase B: in_proj GEMM over 2 k-tiles (weight tile aliases phase A smem) ----
    int c = tid;
    float a2[16];
    #pragma unroll
    for (int l = 0; l < 16; ++l) a2[l] = 0.f;

    #pragma unroll 1
    for (int kt = 0; kt < 2; ++kt) {
        for (int i = tid; i < 256 * 32; i += 256) {
            int cc = i >> 5, kl = i & 31;
            s_w2[kl * 257 + cc] = inw[cc * 64 + kt * 32 + kl];
        }
        __syncthreads();
        #pragma unroll 2
        for (int k4 = 0; k4 < 8; ++k4) {
            float w0 = s_w2[(k4 * 4 + 0) * 257 + c];
            float w1 = s_w2[(k4 * 4 + 1) * 257 + c];
            float w2 = s_w2[(k4 * 4 + 2) * 257 + c];
            float w3 = s_w2[(k4 * 4 + 3) * 257 + c];
            #pragma unroll
            for (int l = 0; l < 16; ++l) {
                float4 x = *(const float4*)&s_nrow[l * 68 + kt * 32 + k4 * 4];
                a2[l] += w0 * x.x + w1 * x.y + w2 * x.z + w3 * x.w;
            }
        }
        __syncthreads();
    }
    float bb = inb[c];
    float* xzp = g_xz + ((size_t)(b * LQ + l0)) * 256 + c;
    #pragma unroll
    for (int l = 0; l < 16; ++l) xzp[(size_t)l * 256] = a2[l] + bb;
}

// ================= K2: dwconv + silu + xproj + dtproj + softplus + packing =================
#define K2_SMEM_FLOATS 19264
#define K2_SMEM_BYTES  (K2_SMEM_FLOATS * 4)

__global__ void __launch_bounds__(256) k2_conv_xproj(
    const float* __restrict__ convw,
    const float* __restrict__ convb,
    const float* __restrict__ xprojw,
    const float* __restrict__ dtw,
    const float* __restrict__ dtb,
    const float* __restrict__ Dpw)
{
    extern __shared__ float sm[];
    float* s_xin   = sm;
    float* s_convw = sm + 47 * 128;
    float* s_xw    = sm;
    float* s_dbc   = sm + 68 * 128;
    float* s_xc    = sm + 10912;
    float* s_z     = sm + 15136;

    int b  = blockIdx.x >> 6;
    int l0 = (blockIdx.x & 63) << 5;
    int tid = threadIdx.x;

    for (int i = tid; i < 128 * 16; i += 256) s_convw[i] = convw[i];
    for (int i = tid; i < 47 * 128; i += 256) {
        int r = i >> 7, ch = i & 127;
        int l = l0 - 15 + r;
        s_xin[i] = (l >= 0) ? g_xz[((size_t)(b * LQ + l)) * 256 + ch] : 0.f;
    }
    for (int i = tid; i < 32 * 128; i += 256) {
        int l = i >> 7, ch = i & 127;
        s_z[l * 129 + ch] = g_xz[((size_t)(b * LQ + l0 + l)) * 256 + 128 + ch];
    }
    __syncthreads();

    for (int i = tid; i < 32 * 128; i += 256) {
        int l = i >> 7, ch = i & 127;
        float acc = convb[ch];
        #pragma unroll
        for (int j = 0; j < DCV; ++j)
            acc += s_convw[ch * DCV + j] * s_xin[(l + j) * 128 + ch];
        float sg = 1.f / (1.f + __expf(-acc));
        s_xc[l * 132 + ch] = acc * sg;
    }
    __syncthreads();

    for (int i = tid; i < 68 * 128; i += 256) s_xw[i] = xprojw[i];
    __syncthreads();

    {
        int l = tid & 31, rg = tid >> 5;
        if (rg * 9 < RQ) {
            float acc[9];
            #pragma unroll
            for (int r = 0; r < 9; ++r) acc[r] = 0.f;
            const float4* xc4 = (const float4*)(s_xc + l * 132);
            #pragma unroll 1
            for (int kc = 0; kc < 4; ++kc) {
                float4 xr[8];
                #pragma unroll
                for (int q = 0; q < 8; ++q) xr[q] = xc4[kc * 8 + q];
                #pragma unroll
                for (int rr = 0; rr < 9; ++rr) {
                    int r = rg * 9 + rr;
                    if (r < RQ) {
                        const float4* w4 = (const float4*)(s_xw + r * 128 + kc * 32);
                        float a = acc[rr];
                        #pragma unroll
                        for (int q = 0; q < 8; ++q) {
                            float4 w = w4[q];
                            a += w.x * xr[q].x + w.y * xr[q].y + w.z * xr[q].z + w.w * xr[q].w;
                        }
                        acc[rr] = a;
                    }
                }
            }
            #pragma unroll
            for (int rr = 0; rr < 9; ++rr) {
                int r = rg * 9 + rr;
                if (r < RQ) s_dbc[l * 69 + r] = acc[rr];
            }
        }
    }
    __syncthreads();

    for (int i = tid; i < 32 * 128; i += 256) {
        int e = i >> 5, l = i & 31;
        const float* dr = s_dbc + l * 69;
        float4 wv = __ldg((const float4*)(dtw + e * 4));
        float v = dr[0] * wv.x + dr[1] * wv.y + dr[2] * wv.z + dr[3] * wv.w + dtb[e];
        float delta = (v > 20.f) ? v : log1pf(__expf(v));
        float xcv = s_xc[l * 132 + e];
        float z  = s_z[l * 129 + e];
        float gz = z / (1.f + __expf(-z));
        size_t oidx = ((size_t)(b * ED + e)) * LQ + l0 + l;
        g_dx2[oidx]   = make_float2(delta, delta * xcv);
        g_gate2[oidx] = make_float2(gz, Dpw[e] * xcv * gz);
    }
    // pack {B,C} fp16x2 in (b, chunk, t, n) layout — n fastest, coalesced stores
    {
        int chunk = l0 >> 8;       // CH = 256
        int tin   = l0 & (CH - 1);
        for (int i = tid; i < 32 * 32; i += 256) {
            int l = i >> 5, n = i & 31;
            const float* dr = s_dbc + l * 69;
            __half2 bc = __floats2half2_rn(dr[DTR + n], dr[DTR + NQ + n]);   // lo=B, hi=C
            g_bcTp[(((size_t)(b * NCH + chunk)) * CH + tin + l) * NQ + n] = *(unsigned*)&bc;
        }
    }
}

// ================= K3a: local chunk scan (carry out; analytic P) =================
// smem: s_bc uint [CH][NQ] (32KB) + s_dx [EG][CH] float2 (32KB)
#define K3A_SMEM_BYTES (CH * NQ * 4 + EG * CH * 8)

__global__ void __launch_bounds__(512) k3a_scan_local(const float* __restrict__ Alog)
{
    extern __shared__ char sma_raw[];
    unsigned* s_bc = (unsigned*)sma_raw;                        // [t][n]
    float2 (*s_dx)[CH] = (float2(*)[CH])(sma_raw + CH * NQ * 4);

    int eg = blockIdx.x & 7;
    int c  = (blockIdx.x >> 3) & 7;
    int b  = blockIdx.x >> 6;
    int tid = threadIdx.x, lane = tid & 31, w = tid >> 5;
    int e = eg * EG + w;

    float sumd;
    {
        const uint4* src = (const uint4*)(g_bcTp + (((size_t)(b * NCH + c)) * CH) * NQ);
        uint4* dst = (uint4*)s_bc;
        #pragma unroll
        for (int i = 0; i < 4; ++i) dst[tid + i * 512] = __ldg(src + tid + i * 512);

        const float4* dsrc = (const float4*)(g_dx2 + ((size_t)(b * ED + e)) * LQ + c * CH);
        float sd = 0.f;
        #pragma unroll
        for (int k = 0; k < CH / 64; ++k) {
            float4 f = __ldg(dsrc + k * 32 + lane);
            *(float4*)(&s_dx[w][(k * 32 + lane) * 2]) = f;
            sd += f.x + f.z;
        }
        #pragma unroll
        for (int s = 16; s; s >>= 1) sd += __shfl_xor_sync(~0u, sd, s);
        sumd = sd;
    }
    __syncthreads();

    float aA = -__expf(Alog[e * NQ + lane]) * LOG2EF;

    float h = 0.f;
    #pragma unroll 8
    for (int j = 0; j < CH; j += 2) {
        float4 dd = *(const float4*)(&s_dx[w][j]);      // steps j, j+1 (broadcast)
        unsigned u0 = s_bc[j * NQ + lane];              // conflict-free LDS.32
        unsigned u1 = s_bc[(j + 1) * NQ + lane];
        float B0 = __half2float(*(const __half*)&u0);   // low half = B
        float B1 = __half2float(*(const __half*)&u1);
        float dA0 = ex2(dd.x * aA);
        h = fmaf(dA0, h, dd.y * B0);
        float dA1 = ex2(dd.z * aA);
        h = fmaf(dA1, h, dd.w * B1);
    }
    float P = ex2(aA * sumd);                           // = prod_t exp2(aA*delta_t)
    g_carry[(((size_t)(b * ED + e)) * NCH + c) * NQ + lane] = make_float2(h, P);
}

// ================= K3c: combine prologue + rescan + multi-reduce (raw y out) =================
// smem: s_bc uint [CH][NQ] (32KB) + s_dx [EG][CH] float2 (32KB)
#define K3C_SMEM_BYTES (CH * NQ * 4 + EG * CH * 8)

__global__ void __launch_bounds__(512) k3c_scan_out(const float* __restrict__ Alog)
{
    extern __shared__ char smc_raw[];
    unsigned* s_bc = (unsigned*)smc_raw;                        // [t][n]
    float2 (*s_dx)[CH] = (float2(*)[CH])(smc_raw + CH * NQ * 4);

    int eg = blockIdx.x & 7;
    int c  = (blockIdx.x >> 3) & 7;
    int b  = blockIdx.x >> 6;
    int tid = threadIdx.x, lane = tid & 31, w = tid >> 5;
    int e = eg * EG + w;

    {
        const uint4* src = (const uint4*)(g_bcTp + (((size_t)(b * NCH + c)) * CH) * NQ);
        uint4* dst = (uint4*)s_bc;
        #pragma unroll
        for (int i = 0; i < 4; ++i) dst[tid + i * 512] = __ldg(src + tid + i * 512);

        const float4* dsrc = (const float4*)(g_dx2 + ((size_t)(b * ED + e)) * LQ + c * CH);
        #pragma unroll
        for (int k = 0; k < CH / 64; ++k)
            *(float4*)(&s_dx[w][(k * 32 + lane) * 2]) = __ldg(dsrc + k * 32 + lane);
    }

    float h = 0.f;
    if (c > 0) {
        const float2* cp = g_carry + (((size_t)(b * ED + e)) * NCH) * NQ + lane;
        #pragma unroll
        for (int cc = 0; cc < NCH - 1; ++cc) {
            if (cc >= c) break;
            float2 v = __ldg(cp + (size_t)cc * NQ);
            h = fmaf(v.y, h, v.x);
        }
    }
    __syncthreads();

    float aA = -__expf(Alog[e * NQ + lane]) * LOG2EF;
    float* yp = g_yout + ((size_t)(b * ED + e)) * LQ + c * CH;

    #pragma unroll 1
    for (int t0 = 0; t0 < CH; t0 += 32) {
        float v[32];
        #pragma unroll
        for (int j = 0; j < 32; j += 2) {
            float4 dd = *(const float4*)(&s_dx[w][t0 + j]);      // dx steps j, j+1
            unsigned u0 = s_bc[(t0 + j) * NQ + lane];            // conflict-free
            unsigned u1 = s_bc[(t0 + j + 1) * NQ + lane];
            float2 bc0 = __half22float2(*(const __half2*)&u0);
            float2 bc1 = __half22float2(*(const __half2*)&u1);
            float dA0 = ex2(dd.x * aA);
            h = fmaf(dA0, h, dd.y * bc0.x);
            v[j] = h * bc0.y;
            float dA1 = ex2(dd.z * aA);
            h = fmaf(dA1, h, dd.w * bc1.x);
            v[j + 1] = h * bc1.y;
        }
        // butterfly-transpose multi-reduce: lane L ends with sum for step t0+L
        #pragma unroll
        for (int d = 16; d >= 1; d >>= 1) {
            #pragma unroll
            for (int j = 0; j < d; ++j) {
                float send  = (lane & d) ? v[j] : v[j + d];
                float other = __shfl_xor_sync(~0u, send, d);
                float keep  = (lane & d) ? v[j + d] : v[j];
                v[j] = keep + other;
            }
        }
        yp[t0 + lane] = v[0];
    }
}

// ================= final classifier head =================
__global__ void __launch_bounds__(128) k_final(
    const float* __restrict__ fcw, const float* __restrict__ fcb, float* __restrict__ out)
{
    int b = threadIdx.x >> 5, lane = threadIdx.x & 31;
    float s = 0.f;
    #pragma unroll
    for (int j = 0; j < 4; ++j) {
        int e = lane + 32 * j;
        size_t idx = ((size_t)(b * 128 + e)) * LQ + (LQ - 1);
        float yr = g_yout[idx];
        float2 g = g_gate2[idx];
        s += fmaf(yr, g.x, g.y) * fcw[e];
    }
    #pragma unroll
    for (int d = 16; d; d >>= 1) s += __shfl_xor_sync(~0u, s, d);
    if (lane == 0) out[b] = s + fcb[0];
}

// ================= launch =================
extern "C" void kernel_launch(void* const* d_in, const int* in_sizes, int n_in,
                              void* d_out, int out_size)
{
    const float* x        = (const float*)d_in[0];
    const float* in_w     = (const float*)d_in[1];
    const float* in_b     = (const float*)d_in[2];
    const float* conv_w   = (const float*)d_in[3];
    const float* conv_b   = (const float*)d_in[4];
    const float* xproj_w  = (const float*)d_in[5];
    const float* dtproj_w = (const float*)d_in[6];
    const float* dtproj_b = (const float*)d_in[7];
    const float* A_log    = (const float*)d_in[8];
    const float* Dp       = (const float*)d_in[9];
    const float* outp_w   = (const float*)d_in[10];
    const float* outp_b   = (const float*)d_in[11];
    const float* norm_w   = (const float*)d_in[12];
    const float* fc_w     = (const float*)d_in[13];
    const float* fc_b     = (const float*)d_in[14];
    float* out = (float*)d_out;

    (void)in_sizes; (void)n_in; (void)out_size;

    cudaFuncSetAttribute(k1_rms_inproj,  cudaFuncAttributeMaxDynamicSharedMemorySize, K1_SMEM_BYTES);
    cudaFuncSetAttribute(k41_out_rms_in, cudaFuncAttributeMaxDynamicSharedMemorySize, K41_SMEM_BYTES);
    cudaFuncSetAttribute(k2_conv_xproj,  cudaFuncAttributeMaxDynamicSharedMemorySize, K2_SMEM_BYTES);
    cudaFuncSetAttribute(k3a_scan_local, cudaFuncAttributeMaxDynamicSharedMemorySize, K3A_SMEM_BYTES);
    cudaFuncSetAttribute(k3c_scan_out,   cudaFuncAttributeMaxDynamicSharedMemorySize, K3C_SMEM_BYTES);

    float* gh = nullptr;
    cudaGetSymbolAddress((void**)&gh, g_h);

    for (int i = 0; i < 4; ++i) {
        if (i == 0) {
            k1_rms_inproj<<<256, 256, K1_SMEM_BYTES>>>(x, in_w, in_b, norm_w);
        } else {
            const float* hin = (i == 1) ? x : gh;
            k41_out_rms_in<<<512, 256, K41_SMEM_BYTES>>>(
                outp_w + (size_t)(i - 1) * DM * ED,
                outp_b + (size_t)(i - 1) * DM,
                hin, gh,
                in_w + (size_t)i * 2 * ED * DM,
                in_b + (size_t)i * 2 * ED,
                norm_w + (size_t)i * DM);
        }
        k2_conv_xproj<<<256, 256, K2_SMEM_BYTES>>>(
            conv_w   + (size_t)i * ED * DCV,
            conv_b   + (size_t)i * ED,
            xproj_w  + (size_t)i * RQ * ED,
            dtproj_w + (size_t)i * ED * DTR,
            dtproj_b + (size_t)i * ED,
            Dp       + (size_t)i * ED);
        const float* Al = A_log + (size_t)i * ED * NQ;
        k3a_scan_local<<<256, 512, K3A_SMEM_BYTES>>>(Al);
        k3c_scan_out<<<256, 512, K3C_SMEM_BYTES>>>(Al);
    }
    k_final<<<1, 128>>>(fc_w, fc_b, out);
}

// round 15
// speedup vs baseline: 1.0456x; 1.0456x over previous
#include <cuda_runtime.h>
#include <cuda_fp16.h>

#define BQ 4
#define LQ 2048
#define DM 64
#define ED 128
#define NQ 32
#define DCV 16
#define DTR 4
#define RQ 68            // DTR + 2*N
#define EPSQ 1e-5f
#define LOG2EF 1.4426950408889634f

#define CH 256           // steps per chunk (k3)
#define NCH 8            // chunks
#define EG 16            // e-channels per scan block

// ---------------- scratch (device globals; no allocation allowed) ----------------
__device__ float  g_h[BQ * LQ * DM];               // residual stream
__device__ float  g_xz[BQ * LQ * 2 * ED];          // in_proj output (b,l,2e)
__device__ float2 g_dx2[BQ * ED * LQ];             // {delta, delta*xc}  (b,e,l)
__device__ float2 g_gate2[BQ * ED * LQ];           // {silu(z), Dp*xc*silu(z)} (b,e,l)
__device__ unsigned g_bcTp[BQ * NCH * CH * NQ];    // {B lo, C hi} fp16x2, (b,chunk,t,n)
__device__ float  g_yout[BQ * ED * LQ];            // GATED scan output (b,e,l)
__device__ float2 g_carry[BQ * ED * NCH * NQ];     // {h_final, P}

__device__ __forceinline__ float ex2(float x) {
    float r; asm("ex2.approx.ftz.f32 %0, %1;" : "=f"(r) : "f"(x)); return r;
}

// ================= K1: rmsnorm + in_proj (layer 0 only) =================
#define K1_SMEM_FLOATS (64 * 257 + 32 * 68)
#define K1_SMEM_BYTES  (K1_SMEM_FLOATS * 4)

__global__ void __launch_bounds__(256, 2) k1_rms_inproj(
    const float* __restrict__ hin,
    const float* __restrict__ inw,   // (256, 64)
    const float* __restrict__ inb,
    const float* __restrict__ nw)
{
    extern __shared__ float sm1[];
    float* s_w    = sm1;              // [k=64][c=256] pad 257
    float* s_nrow = sm1 + 64 * 257;   // [l=32][k=64] pad 68

    int b  = blockIdx.x >> 6;
    int l0 = (blockIdx.x & 63) << 5;
    int tid = threadIdx.x;
    int lane = tid & 31, wid = tid >> 5;

    for (int i = tid; i < 256 * 64; i += 256)
        s_w[(i & 63) * 257 + (i >> 6)] = inw[i];

    #pragma unroll
    for (int il = 0; il < 4; ++il) {
        int l = wid * 4 + il;
        const float* hr = hin + ((size_t)(b * LQ + l0 + l)) * DM;
        float v0 = hr[lane], v1 = hr[lane + 32];
        float ss = v0 * v0 + v1 * v1;
        #pragma unroll
        for (int s = 16; s; s >>= 1) ss += __shfl_xor_sync(~0u, ss, s);
        float r = rsqrtf(ss * (1.0f / DM) + EPSQ);
        s_nrow[l * 68 + lane]      = v0 * r * nw[lane];
        s_nrow[l * 68 + lane + 32] = v1 * r * nw[lane + 32];
    }
    __syncthreads();

    int c = tid;
    float acc[32];
    #pragma unroll
    for (int l = 0; l < 32; ++l) acc[l] = 0.f;

    #pragma unroll 2
    for (int k4 = 0; k4 < 16; ++k4) {
        float w0 = s_w[(k4 * 4 + 0) * 257 + c];
        float w1 = s_w[(k4 * 4 + 1) * 257 + c];
        float w2 = s_w[(k4 * 4 + 2) * 257 + c];
        float w3 = s_w[(k4 * 4 + 3) * 257 + c];
        #pragma unroll
        for (int l = 0; l < 32; ++l) {
            float4 x = *(const float4*)&s_nrow[l * 68 + k4 * 4];
            acc[l] += w0 * x.x + w1 * x.y + w2 * x.z + w3 * x.w;
        }
    }
    float bb = inb[c];
    float* xzp = g_xz + ((size_t)(b * LQ + l0)) * 256 + c;
    #pragma unroll
    for (int l = 0; l < 32; ++l) xzp[(size_t)l * 256] = acc[l] + bb;
}

// ================= K41: out_proj + residual + rmsnorm + in_proj (fused; y pre-gated) =================
#define K41_SMEM_FLOATS 18624
#define K41_SMEM_BYTES  (K41_SMEM_FLOATS * 4)

__global__ void __launch_bounds__(256, 2) k41_out_rms_in(
    const float* __restrict__ ow,    // (64, 128)  layer i-1
    const float* __restrict__ ob,
    const float* __restrict__ hin,
    float* __restrict__ hout,        // g_h
    const float* __restrict__ inw,   // (256, 64)  layer i
    const float* __restrict__ inb,
    const float* __restrict__ nw)
{
    extern __shared__ float smf[];
    float* s_wT   = smf;              // [k=128][d=64] pad 65
    float* s_yT   = smf + 128 * 65;   // [e=128][l=32] pad 36
    float* s_w    = smf;              // phase B: [k=64][c=256] pad 257
    float* s_nrow = smf + 16448;      // [l=32][k=64] pad 68

    int b  = blockIdx.x >> 6;
    int l0 = (blockIdx.x & 63) << 5;
    int tid = threadIdx.x;
    int lane = tid & 31, wid = tid >> 5;

    for (int i = tid; i < 64 * 128; i += 256)
        s_wT[(i & 127) * 65 + (i >> 7)] = ow[i];
    for (int i = tid; i < 128 * 32; i += 256) {
        int e = i >> 5, l = i & 31;
        s_yT[e * 36 + l] = g_yout[((size_t)(b * ED + e)) * LQ + l0 + l];  // pre-gated
    }
    __syncthreads();

    int d = tid & 63, lg = tid >> 6;
    float acc[8];
    #pragma unroll
    for (int j = 0; j < 8; ++j) acc[j] = 0.f;

    #pragma unroll 4
    for (int k = 0; k < 128; ++k) {
        float w = s_wT[k * 65 + d];
        float4 x0 = *(const float4*)&s_yT[k * 36 + lg * 8];
        float4 x1 = *(const float4*)&s_yT[k * 36 + lg * 8 + 4];
        acc[0] += w * x0.x; acc[1] += w * x0.y; acc[2] += w * x0.z; acc[3] += w * x0.w;
        acc[4] += w * x1.x; acc[5] += w * x1.y; acc[6] += w * x1.z; acc[7] += w * x1.w;
    }

    float bias = ob[d];
    #pragma unroll
    for (int j = 0; j < 8; ++j) {
        int l = lg * 8 + j;
        size_t idx = ((size_t)(b * LQ + l0 + l)) * DM + d;
        float hv = hin[idx] + bias + acc[j];
        hout[idx] = hv;
        s_nrow[l * 68 + d] = hv;
    }
    __syncthreads();

    for (int i = tid; i < 256 * 64; i += 256)
        s_w[(i & 63) * 257 + (i >> 6)] = inw[i];

    #pragma unroll
    for (int il = 0; il < 4; ++il) {
        int l = wid * 4 + il;
        float v0 = s_nrow[l * 68 + lane], v1 = s_nrow[l * 68 + lane + 32];
        float ss = v0 * v0 + v1 * v1;
        #pragma unroll
        for (int s = 16; s; s >>= 1) ss += __shfl_xor_sync(~0u, ss, s);
        float r = rsqrtf(ss * (1.0f / DM) + EPSQ);
        s_nrow[l * 68 + lane]      = v0 * r * nw[lane];
        s_nrow[l * 68 + lane + 32] = v1 * r * nw[lane + 32];
    }
    __syncthreads();

    int c = tid;
    float a2[32];
    #pragma unroll
    for (int l = 0; l < 32; ++l) a2[l] = 0.f;

    #pragma unroll 2
    for (int k4 = 0; k4 < 16; ++k4) {
        float w0 = s_w[(k4 * 4 + 0) * 257 + c];
        float w1 = s_w[(k4 * 4 + 1) * 257 + c];
        float w2 = s_w[(k4 * 4 + 2) * 257 + c];
        float w3 = s_w[(k4 * 4 + 3) * 257 + c];
        #pragma unroll
        for (int l = 0; l < 32; ++l) {
            float4 x = *(const float4*)&s_nrow[l * 68 + k4 * 4];
            a2[l] += w0 * x.x + w1 * x.y + w2 * x.z + w3 * x.w;
        }
    }
    float bb = inb[c];
    float* xzp = g_xz + ((size_t)(b * LQ + l0)) * 256 + c;
    #pragma unroll
    for (int l = 0; l < 32; ++l) xzp[(size_t)l * 256] = a2[l] + bb;
}

// ================= K2: dwconv + silu + xproj + dtproj + softplus + packing =================
#define K2_SMEM_FLOATS 19264
#define K2_SMEM_BYTES  (K2_SMEM_FLOATS * 4)

__global__ void __launch_bounds__(256) k2_conv_xproj(
    const float* __restrict__ convw,
    const float* __restrict__ convb,
    const float* __restrict__ xprojw,
    const float* __restrict__ dtw,
    const float* __restrict__ dtb,
    const float* __restrict__ Dpw)
{
    extern __shared__ float sm[];
    float* s_xin   = sm;
    float* s_convw = sm + 47 * 128;
    float* s_xw    = sm;
    float* s_dbc   = sm + 68 * 128;
    float* s_xc    = sm + 10912;
    float* s_z     = sm + 15136;

    int b  = blockIdx.x >> 6;
    int l0 = (blockIdx.x & 63) << 5;
    int tid = threadIdx.x;

    for (int i = tid; i < 128 * 16; i += 256) s_convw[i] = convw[i];
    for (int i = tid; i < 47 * 128; i += 256) {
        int r = i >> 7, ch = i & 127;
        int l = l0 - 15 + r;
        s_xin[i] = (l >= 0) ? g_xz[((size_t)(b * LQ + l)) * 256 + ch] : 0.f;
    }
    for (int i = tid; i < 32 * 128; i += 256) {
        int l = i >> 7, ch = i & 127;
        s_z[l * 129 + ch] = g_xz[((size_t)(b * LQ + l0 + l)) * 256 + 128 + ch];
    }
    __syncthreads();

    for (int i = tid; i < 32 * 128; i += 256) {
        int l = i >> 7, ch = i & 127;
        float acc = convb[ch];
        #pragma unroll
        for (int j = 0; j < DCV; ++j)
            acc += s_convw[ch * DCV + j] * s_xin[(l + j) * 128 + ch];
        float sg = 1.f / (1.f + __expf(-acc));
        s_xc[l * 132 + ch] = acc * sg;
    }
    __syncthreads();

    for (int i = tid; i < 68 * 128; i += 256) s_xw[i] = xprojw[i];
    __syncthreads();

    {
        int l = tid & 31, rg = tid >> 5;
        if (rg * 9 < RQ) {
            float acc[9];
            #pragma unroll
            for (int r = 0; r < 9; ++r) acc[r] = 0.f;
            const float4* xc4 = (const float4*)(s_xc + l * 132);
            #pragma unroll 1
            for (int kc = 0; kc < 4; ++kc) {
                float4 xr[8];
                #pragma unroll
                for (int q = 0; q < 8; ++q) xr[q] = xc4[kc * 8 + q];
                #pragma unroll
                for (int rr = 0; rr < 9; ++rr) {
                    int r = rg * 9 + rr;
                    if (r < RQ) {
                        const float4* w4 = (const float4*)(s_xw + r * 128 + kc * 32);
                        float a = acc[rr];
                        #pragma unroll
                        for (int q = 0; q < 8; ++q) {
                            float4 w = w4[q];
                            a += w.x * xr[q].x + w.y * xr[q].y + w.z * xr[q].z + w.w * xr[q].w;
                        }
                        acc[rr] = a;
                    }
                }
            }
            #pragma unroll
            for (int rr = 0; rr < 9; ++rr) {
                int r = rg * 9 + rr;
                if (r < RQ) s_dbc[l * 69 + r] = acc[rr];
            }
        }
    }
    __syncthreads();

    for (int i = tid; i < 32 * 128; i += 256) {
        int e = i >> 5, l = i & 31;
        const float* dr = s_dbc + l * 69;
        float4 wv = __ldg((const float4*)(dtw + e * 4));
        float v = dr[0] * wv.x + dr[1] * wv.y + dr[2] * wv.z + dr[3] * wv.w + dtb[e];
        float delta = (v > 20.f) ? v : log1pf(__expf(v));
        float xcv = s_xc[l * 132 + e];
        float z  = s_z[l * 129 + e];
        float gz = z / (1.f + __expf(-z));
        size_t oidx = ((size_t)(b * ED + e)) * LQ + l0 + l;
        g_dx2[oidx]   = make_float2(delta, delta * xcv);
        g_gate2[oidx] = make_float2(gz, Dpw[e] * xcv * gz);
    }
    // pack {B,C} fp16x2 in (b, chunk, t, n) layout — n fastest, coalesced stores
    {
        int chunk = l0 >> 8;       // CH = 256
        int tin   = l0 & (CH - 1);
        for (int i = tid; i < 32 * 32; i += 256) {
            int l = i >> 5, n = i & 31;
            const float* dr = s_dbc + l * 69;
            __half2 bc = __floats2half2_rn(dr[DTR + n], dr[DTR + NQ + n]);   // lo=B, hi=C
            g_bcTp[(((size_t)(b * NCH + chunk)) * CH + tin + l) * NQ + n] = *(unsigned*)&bc;
        }
    }
}

// ================= K3a: local chunk scan (carry out; analytic P) =================
// smem: s_bc uint [CH][NQ] (32KB) + s_dx [EG][CH] float2 (32KB)
#define K3A_SMEM_BYTES (CH * NQ * 4 + EG * CH * 8)

__global__ void __launch_bounds__(512) k3a_scan_local(const float* __restrict__ Alog)
{
    extern __shared__ char sma_raw[];
    unsigned* s_bc = (unsigned*)sma_raw;                        // [t][n]
    float2 (*s_dx)[CH] = (float2(*)[CH])(sma_raw + CH * NQ * 4);

    int eg = blockIdx.x & 7;
    int c  = (blockIdx.x >> 3) & 7;
    int b  = blockIdx.x >> 6;
    int tid = threadIdx.x, lane = tid & 31, w = tid >> 5;
    int e = eg * EG + w;

    float sumd;
    {
        const uint4* src = (const uint4*)(g_bcTp + (((size_t)(b * NCH + c)) * CH) * NQ);
        uint4* dst = (uint4*)s_bc;
        #pragma unroll
        for (int i = 0; i < 4; ++i) dst[tid + i * 512] = __ldg(src + tid + i * 512);

        const float4* dsrc = (const float4*)(g_dx2 + ((size_t)(b * ED + e)) * LQ + c * CH);
        float sd = 0.f;
        #pragma unroll
        for (int k = 0; k < CH / 64; ++k) {
            float4 f = __ldg(dsrc + k * 32 + lane);
            *(float4*)(&s_dx[w][(k * 32 + lane) * 2]) = f;
            sd += f.x + f.z;
        }
        #pragma unroll
        for (int s = 16; s; s >>= 1) sd += __shfl_xor_sync(~0u, sd, s);
        sumd = sd;
    }
    __syncthreads();

    float aA = -__expf(Alog[e * NQ + lane]) * LOG2EF;

    float h = 0.f;
    #pragma unroll 8
    for (int j = 0; j < CH; j += 2) {
        float4 dd = *(const float4*)(&s_dx[w][j]);      // steps j, j+1 (broadcast)
        unsigned u0 = s_bc[j * NQ + lane];              // conflict-free LDS.32
        unsigned u1 = s_bc[(j + 1) * NQ + lane];
        float B0 = __half2float(*(const __half*)&u0);   // low half = B
        float B1 = __half2float(*(const __half*)&u1);
        float dA0 = ex2(dd.x * aA);
        h = fmaf(dA0, h, dd.y * B0);
        float dA1 = ex2(dd.z * aA);
        h = fmaf(dA1, h, dd.w * B1);
    }
    float P = ex2(aA * sumd);                           // = prod_t exp2(aA*delta_t)
    g_carry[(((size_t)(b * ED + e)) * NCH + c) * NQ + lane] = make_float2(h, P);
}

// ================= K3c: combine prologue + rescan + multi-reduce + gate =================
// smem: s_bc uint [CH][NQ] (32KB) + s_dx [EG][CH] float2 (32KB)
#define K3C_SMEM_BYTES (CH * NQ * 4 + EG * CH * 8)

__global__ void __launch_bounds__(512) k3c_scan_out(const float* __restrict__ Alog)
{
    extern __shared__ char smc_raw[];
    unsigned* s_bc = (unsigned*)smc_raw;                        // [t][n]
    float2 (*s_dx)[CH] = (float2(*)[CH])(smc_raw + CH * NQ * 4);

    int eg = blockIdx.x & 7;
    int c  = (blockIdx.x >> 3) & 7;
    int b  = blockIdx.x >> 6;
    int tid = threadIdx.x, lane = tid & 31, w = tid >> 5;
    int e = eg * EG + w;

    {
        const uint4* src = (const uint4*)(g_bcTp + (((size_t)(b * NCH + c)) * CH) * NQ);
        uint4* dst = (uint4*)s_bc;
        #pragma unroll
        for (int i = 0; i < 4; ++i) dst[tid + i * 512] = __ldg(src + tid + i * 512);

        const float4* dsrc = (const float4*)(g_dx2 + ((size_t)(b * ED + e)) * LQ + c * CH);
        #pragma unroll
        for (int k = 0; k < CH / 64; ++k)
            *(float4*)(&s_dx[w][(k * 32 + lane) * 2]) = __ldg(dsrc + k * 32 + lane);
    }

    float h = 0.f;
    if (c > 0) {
        const float2* cp = g_carry + (((size_t)(b * ED + e)) * NCH) * NQ + lane;
        #pragma unroll
        for (int cc = 0; cc < NCH - 1; ++cc) {
            if (cc >= c) break;
            float2 v = __ldg(cp + (size_t)cc * NQ);
            h = fmaf(v.y, h, v.x);
        }
    }
    __syncthreads();

    float aA = -__expf(Alog[e * NQ + lane]) * LOG2EF;
    const float2* gtp = g_gate2 + ((size_t)(b * ED + e)) * LQ + c * CH;
    float* yp = g_yout + ((size_t)(b * ED + e)) * LQ + c * CH;

    #pragma unroll 1
    for (int t0 = 0; t0 < CH; t0 += 32) {
        float v[32];
        #pragma unroll
        for (int j = 0; j < 32; j += 2) {
            float4 dd = *(const float4*)(&s_dx[w][t0 + j]);      // dx steps j, j+1
            unsigned u0 = s_bc[(t0 + j) * NQ + lane];            // conflict-free
            unsigned u1 = s_bc[(t0 + j + 1) * NQ + lane];
            float2 bc0 = __half22float2(*(const __half2*)&u0);
            float2 bc1 = __half22float2(*(const __half2*)&u1);
            float dA0 = ex2(dd.x * aA);
            h = fmaf(dA0, h, dd.y * bc0.x);
            v[j] = h * bc0.y;
            float dA1 = ex2(dd.z * aA);
            h = fmaf(dA1, h, dd.w * bc1.x);
            v[j + 1] = h * bc1.y;
        }
        // butterfly-transpose multi-reduce: lane L ends with sum for step t0+L
        #pragma unroll
        for (int d = 16; d >= 1; d >>= 1) {
            #pragma unroll
            for (int j = 0; j < d; ++j) {
                float send  = (lane & d) ? v[j] : v[j + d];
                float other = __shfl_xor_sync(~0u, send, d);
                float keep  = (lane & d) ? v[j + d] : v[j];
                v[j] = keep + other;
            }
        }
        float2 g = __ldg(gtp + t0 + lane);                       // coalesced
        yp[t0 + lane] = fmaf(v[0], g.x, g.y);                    // gated output
    }
}

// ================= final classifier head =================
__global__ void __launch_bounds__(128) k_final(
    const float* __restrict__ fcw, const float* __restrict__ fcb, float* __restrict__ out)
{
    int b = threadIdx.x >> 5, lane = threadIdx.x & 31;
    float s = 0.f;
    #pragma unroll
    for (int j = 0; j < 4; ++j) {
        int e = lane + 32 * j;
        s += g_yout[((size_t)(b * 128 + e)) * LQ + (LQ - 1)] * fcw[e];
    }
    #pragma unroll
    for (int d = 16; d; d >>= 1) s += __shfl_xor_sync(~0u, s, d);
    if (lane == 0) out[b] = s + fcb[0];
}

// ================= launch =================
extern "C" void kernel_launch(void* const* d_in, const int* in_sizes, int n_in,
                              void* d_out, int out_size)
{
    const float* x        = (const float*)d_in[0];
    const float* in_w     = (const float*)d_in[1];
    const float* in_b     = (const float*)d_in[2];
    const float* conv_w   = (const float*)d_in[3];
    const float* conv_b   = (const float*)d_in[4];
    const float* xproj_w  = (const float*)d_in[5];
    const float* dtproj_w = (const float*)d_in[6];
    const float* dtproj_b = (const float*)d_in[7];
    const float* A_log    = (const float*)d_in[8];
    const float* Dp       = (const float*)d_in[9];
    const float* outp_w   = (const float*)d_in[10];
    const float* outp_b   = (const float*)d_in[11];
    const float* norm_w   = (const float*)d_in[12];
    const float* fc_w     = (const float*)d_in[13];
    const float* fc_b     = (const float*)d_in[14];
    float* out = (float*)d_out;

    (void)in_sizes; (void)n_in; (void)out_size;

    cudaFuncSetAttribute(k1_rms_inproj,  cudaFuncAttributeMaxDynamicSharedMemorySize, K1_SMEM_BYTES);
    cudaFuncSetAttribute(k41_out_rms_in, cudaFuncAttributeMaxDynamicSharedMemorySize, K41_SMEM_BYTES);
    cudaFuncSetAttribute(k2_conv_xproj,  cudaFuncAttributeMaxDynamicSharedMemorySize, K2_SMEM_BYTES);
    cudaFuncSetAttribute(k3a_scan_local, cudaFuncAttributeMaxDynamicSharedMemorySize, K3A_SMEM_BYTES);
    cudaFuncSetAttribute(k3c_scan_out,   cudaFuncAttributeMaxDynamicSharedMemorySize, K3C_SMEM_BYTES);

    float* gh = nullptr;
    cudaGetSymbolAddress((void**)&gh, g_h);

    for (int i = 0; i < 4; ++i) {
        if (i == 0) {
            k1_rms_inproj<<<256, 256, K1_SMEM_BYTES>>>(x, in_w, in_b, norm_w);
        } else {
            const float* hin = (i == 1) ? x : gh;
            k41_out_rms_in<<<256, 256, K41_SMEM_BYTES>>>(
                outp_w + (size_t)(i - 1) * DM * ED,
                outp_b + (size_t)(i - 1) * DM,
                hin, gh,
                in_w + (size_t)i * 2 * ED * DM,
                in_b + (size_t)i * 2 * ED,
                norm_w + (size_t)i * DM);
        }
        k2_conv_xproj<<<256, 256, K2_SMEM_BYTES>>>(
            conv_w   + (size_t)i * ED * DCV,
            conv_b   + (size_t)i * ED,
            xproj_w  + (size_t)i * RQ * ED,
            dtproj_w + (size_t)i * ED * DTR,
            dtproj_b + (size_t)i * ED,
            Dp       + (size_t)i * ED);
        const float* Al = A_log + (size_t)i * ED * NQ;
        k3a_scan_local<<<256, 512, K3A_SMEM_BYTES>>>(Al);
        k3c_scan_out<<<256, 512, K3C_SMEM_BYTES>>>(Al);
    }
    k_final<<<1, 128>>>(fc_w, fc_b, out);
}